// round 1
// baseline (speedup 1.0000x reference)
#include <cuda_runtime.h>
#include <cuda_bf16.h>

// Problem constants
#define E_ 64
#define A_ 8
#define L_ 2048
#define D_ 128
#define H_ 8
#define DK_ 16
#define EA_ (E_*A_)

// ---------------- device scratch (no allocations allowed) ----------------
__device__ float g_Wq_eff[386 * 128];   // (3D+2, D) composed with per-head Wq
__device__ float g_Wk_eff[128 * 128];   // emb-rows only (bias row cancels in softmax)
__device__ float g_Wv_eff[129 * 128];   // includes bias row 128
__device__ float g_wtil [EA_ * H_ * 128]; // per-(e,a) per-head score vector (pre-scaled)

// ---------------- packed f32x2 helpers (2x FFMA throughput on sm_103a) ----
__device__ __forceinline__ unsigned long long pack2(float a, float b) {
    unsigned long long r;
    asm("mov.b64 %0, {%1, %2};" : "=l"(r)
        : "r"(__float_as_uint(a)), "r"(__float_as_uint(b)));
    return r;
}
__device__ __forceinline__ void unpack2(unsigned long long v, float& a, float& b) {
    unsigned int x, y;
    asm("mov.b64 {%0, %1}, %2;" : "=r"(x), "=r"(y) : "l"(v));
    a = __uint_as_float(x); b = __uint_as_float(y);
}
__device__ __forceinline__ unsigned long long fma2(unsigned long long a,
                                                   unsigned long long b,
                                                   unsigned long long c) {
    unsigned long long d;
    asm("fma.rn.f32x2 %0, %1, %2, %3;" : "=l"(d) : "l"(a), "l"(b), "l"(c));
    return d;
}
__device__ __forceinline__ unsigned long long mul2(unsigned long long a,
                                                   unsigned long long b) {
    unsigned long long d;
    asm("mul.rn.f32x2 %0, %1, %2;" : "=l"(d) : "l"(a), "l"(b));
    return d;
}

// ---------------- setup 1: compose projection matrices ----------------
// grid 643 blocks x 128 threads.
//   r <  386        : Wq_eff row r  = Wq_proj[r,:] @ Wq_flat
//   386 <= r < 514  : Wk_eff row r-386 (only emb rows 0..127 of Wk_proj)
//   514 <= r < 643  : Wv_eff row r-514 (all 129 rows of Wv_proj)
// W*_flat[m][h*16+k] = W*[h][m][k]  (W* is [H, D, DK] = [8,128,16])
__global__ void setup_eff(const float* __restrict__ Wq_proj,
                          const float* __restrict__ Wk_proj,
                          const float* __restrict__ Wv_proj,
                          const float* __restrict__ Wq,
                          const float* __restrict__ Wk,
                          const float* __restrict__ Wv) {
    __shared__ float row[128];
    int r = blockIdx.x, t = threadIdx.x;
    const float* proj; const float* W; float* out;
    if (r < 386)      { proj = Wq_proj + r * 128;        W = Wq; out = g_Wq_eff + r * 128; }
    else if (r < 514) { proj = Wk_proj + (r - 386) * 128; W = Wk; out = g_Wk_eff + (r - 386) * 128; }
    else              { proj = Wv_proj + (r - 514) * 128; W = Wv; out = g_Wv_eff + (r - 514) * 128; }
    row[t] = proj[t];
    __syncthreads();
    int h = t >> 4, k = t & 15;
    float acc = 0.f;
    #pragma unroll 8
    for (int m = 0; m < 128; m++)
        acc += row[m] * W[h * 2048 + m * 16 + k];
    out[t] = acc;
}

// ---------------- setup 2: per-(e,a) query -> w-tilde --------------------
// grid 512 blocks x 128 threads.
// qh = q_in @ Wq_eff ; wtil[h][d] = 0.25 * sum_k qh[h*16+k] * Wk_eff[d][h*16+k]
__global__ void setup_wtil(const float* __restrict__ gc,
                           const float* __restrict__ dep,
                           const float* __restrict__ tbd,
                           const float* __restrict__ loadv) {
    __shared__ float qin[386];
    __shared__ float qh[128];
    int ea = blockIdx.x, t = threadIdx.x;
    int e = ea >> 3, a = ea & 7;
    qin[t]       = gc [e * 128 + t];
    qin[128 + t] = dep[e * 128 + t];
    qin[256 + t] = tbd[e * 128 + t];
    if (t == 0) { qin[384] = loadv[e * 8 + a]; qin[385] = (float)a; }
    __syncthreads();
    float acc = 0.f;
    #pragma unroll 2
    for (int j = 0; j < 386; j++)
        acc += qin[j] * g_Wq_eff[j * 128 + t];
    qh[t] = acc;
    __syncthreads();
    int d = t;
    #pragma unroll
    for (int h = 0; h < 8; h++) {
        float w = 0.f;
        #pragma unroll
        for (int k = 0; k < 16; k++)
            w += qh[h * 16 + k] * g_Wk_eff[d * 128 + h * 16 + k];
        g_wtil[(ea * 8 + h) * 128 + d] = w * 0.25f;   // 1/sqrt(DK) folded in
    }
}

// ---------------- main: fused streaming attention ----------------------
// One CTA per (e,a). 8 warps stride the valid rows (l < len).
// Lane layout: h = lane>>2 (head), g = lane&3 (32-wide d-chunk).
// Online softmax per (warp, head); cross-warp combine in SMEM; then
// ctx = (u/denom) @ Wv_eff + bias, out = ctx @ Wo.
__global__ __launch_bounds__(256, 2)
void attn_main(const float* __restrict__ emb,
               const int*   __restrict__ lens,
               const float* __restrict__ Wo,
               float*       __restrict__ out) {
    __shared__ float sm_u[8][8][128];   // [warp][head][d]  32KB
    __shared__ float sm_m[8][8];
    __shared__ float sm_d[8][8];
    __shared__ float sm_scale[8][8];
    __shared__ float sm_den[8];
    __shared__ float sm_uf[8 * 128];
    __shared__ float sm_ctx[128];

    int ea = blockIdx.x;
    int a  = ea & 7;
    int len = lens[ea];
    len = max(1, min(len, L_));

    int tid  = threadIdx.x;
    int warp = tid >> 5, lane = tid & 31;
    int h = lane >> 2, g = lane & 3;

    unsigned long long w2[16], u2[16];
    {
        const ulonglong2* wp =
            (const ulonglong2*)(g_wtil + (ea * 8 + h) * 128 + g * 32);
        #pragma unroll
        for (int i = 0; i < 8; i++) { ulonglong2 v = wp[i]; w2[2*i] = v.x; w2[2*i+1] = v.y; }
    }
    #pragma unroll
    for (int i = 0; i < 16; i++) u2[i] = 0ull;

    float m = __int_as_float(0xff800000);  // -inf
    float denom = 0.f;
    const float* base = emb + (size_t)ea * (L_ * D_) + g * 32;

    for (int l = warp; l < len; l += 8) {
        const ulonglong2* rp = (const ulonglong2*)(base + (size_t)l * D_);
        unsigned long long x2[16];
        #pragma unroll
        for (int i = 0; i < 8; i++) { ulonglong2 v = rp[i]; x2[2*i] = v.x; x2[2*i+1] = v.y; }

        unsigned long long sp2 = 0ull;
        #pragma unroll
        for (int i = 0; i < 16; i++) sp2 = fma2(x2[i], w2[i], sp2);
        float s0, s1; unpack2(sp2, s0, s1);
        float s = s0 + s1;
        s += __shfl_xor_sync(0xffffffffu, s, 1);
        s += __shfl_xor_sync(0xffffffffu, s, 2);

        float p;
        if (s > m) {                       // new running max: rescale (rare, ~ln(n) times)
            float sc = __expf(m - s);      // first iter: exp(-inf) = 0
            denom *= sc;
            unsigned long long sc2 = pack2(sc, sc);
            #pragma unroll
            for (int i = 0; i < 16; i++) u2[i] = mul2(u2[i], sc2);
            m = s;
            p = 1.f;
        } else {
            p = __expf(s - m);
        }
        denom += p;
        unsigned long long p2 = pack2(p, p);
        #pragma unroll
        for (int i = 0; i < 16; i++) u2[i] = fma2(p2, x2[i], u2[i]);
    }

    // dump per-warp partials
    {
        float* up = &sm_u[warp][h][g * 32];
        #pragma unroll
        for (int i = 0; i < 16; i++) {
            float lo, hi; unpack2(u2[i], lo, hi);
            up[2*i] = lo; up[2*i+1] = hi;
        }
        if (g == 0) { sm_m[warp][h] = m; sm_d[warp][h] = denom; }
    }
    __syncthreads();

    // per-head cross-warp max / denom
    if (tid < 8) {
        int hh = tid;
        float mh = __int_as_float(0xff800000);
        #pragma unroll
        for (int w = 0; w < 8; w++) mh = fmaxf(mh, sm_m[w][hh]);
        float dt = 0.f;
        #pragma unroll
        for (int w = 0; w < 8; w++) {
            float sc = __expf(sm_m[w][hh] - mh);  // empty warp: exp(-inf)=0
            sm_scale[w][hh] = sc;
            dt += sm_d[w][hh] * sc;
        }
        sm_den[hh] = dt;
    }
    __syncthreads();

    // combine u across warps
    for (int idx = tid; idx < 1024; idx += 256) {
        int hh = idx >> 7, d = idx & 127;
        float acc = 0.f;
        #pragma unroll
        for (int w = 0; w < 8; w++) acc += sm_u[w][hh][d] * sm_scale[w][hh];
        sm_uf[idx] = acc;
    }
    __syncthreads();

    // ctx[h*16+k] = (u_f[h,:]/den[h]) . Wv_eff[:, h*16+k] + a * Wv_eff[128, h*16+k]
    if (tid < 128) {
        int hh = tid >> 4;
        float acc = 0.f;
        #pragma unroll 8
        for (int d = 0; d < 128; d++)
            acc += sm_uf[hh * 128 + d] * g_Wv_eff[d * 128 + tid];
        sm_ctx[tid] = acc / sm_den[hh] + (float)a * g_Wv_eff[128 * 128 + tid];
    }
    __syncthreads();

    // out[d] = ctx . Wo[:, d]   (Wo is [H][DK][D] -> flat [128][128])
    if (tid < 128) {
        float acc = 0.f;
        #pragma unroll 8
        for (int j = 0; j < 128; j++)
            acc += sm_ctx[j] * Wo[j * 128 + tid];
        out[ea * 128 + tid] = acc;
    }
}

// ---------------- launch ------------------------------------------------
extern "C" void kernel_launch(void* const* d_in, const int* in_sizes, int n_in,
                              void* d_out, int out_size) {
    const float* gc      = (const float*)d_in[0];   // graph_context           [E,D]
    const float* dep     = (const float*)d_in[1];   // depot_embedding         [E,D]
    const float* tbd     = (const float*)d_in[2];   // tbd_node_embedding      [E,D]
    const float* loadv   = (const float*)d_in[3];   // multi_current_load      [E,A]
    const float* emb     = (const float*)d_in[4];   // visited embeddings      [E,A,L,D]
    const int*   lens    = (const int*)  d_in[5];   // visited lens            [E,A]
    const float* Wq_proj = (const float*)d_in[6];   // [386,128]
    const float* Wk_proj = (const float*)d_in[7];   // [129,128]
    const float* Wv_proj = (const float*)d_in[8];   // [129,128]
    const float* Wq      = (const float*)d_in[9];   // [8,128,16]
    const float* Wk      = (const float*)d_in[10];  // [8,128,16]
    const float* Wv      = (const float*)d_in[11];  // [8,128,16]
    const float* Wo      = (const float*)d_in[12];  // [8,16,128]
    float* out = (float*)d_out;                     // [E,A,D]

    setup_eff <<<643, 128>>>(Wq_proj, Wk_proj, Wv_proj, Wq, Wk, Wv);
    setup_wtil<<<EA_, 128>>>(gc, dep, tbd, loadv);
    attn_main <<<EA_, 256>>>(emb, lens, Wo, out);
}

// round 2
// speedup vs baseline: 1.6913x; 1.6913x over previous
#include <cuda_runtime.h>
#include <cuda_bf16.h>

// Problem constants
#define E_ 64
#define A_ 8
#define L_ 2048
#define D_ 128
#define H_ 8
#define DK_ 16
#define EA_ (E_*A_)

typedef unsigned long long ull;

// ---------------- device scratch (no allocations allowed) ----------------
__device__ float g_Wq_eff[386 * 128];   // (3D+2, D) composed with per-head Wq
__device__ float g_Wk_eff[128 * 128];   // emb-rows only (bias row cancels in softmax)
__device__ float g_Wv_eff[129 * 128];   // includes bias row 128
__device__ float g_wtil [EA_ * H_ * 128]; // per-(e,a) per-head score vector (pre-scaled)

// ---------------- packed f32x2 helpers (2x FFMA throughput on sm_103a) ----
__device__ __forceinline__ ull pack2(float a, float b) {
    ull r;
    asm("mov.b64 %0, {%1, %2};" : "=l"(r)
        : "r"(__float_as_uint(a)), "r"(__float_as_uint(b)));
    return r;
}
__device__ __forceinline__ void unpack2(ull v, float& a, float& b) {
    unsigned int x, y;
    asm("mov.b64 {%0, %1}, %2;" : "=r"(x), "=r"(y) : "l"(v));
    a = __uint_as_float(x); b = __uint_as_float(y);
}
__device__ __forceinline__ ull fma2(ull a, ull b, ull c) {
    ull d;
    asm("fma.rn.f32x2 %0, %1, %2, %3;" : "=l"(d) : "l"(a), "l"(b), "l"(c));
    return d;
}
__device__ __forceinline__ ull mul2(ull a, ull b) {
    ull d;
    asm("mul.rn.f32x2 %0, %1, %2;" : "=l"(d) : "l"(a), "l"(b));
    return d;
}

// ---------------- setup 1: compose projection matrices ----------------
__global__ void setup_eff(const float* __restrict__ Wq_proj,
                          const float* __restrict__ Wk_proj,
                          const float* __restrict__ Wv_proj,
                          const float* __restrict__ Wq,
                          const float* __restrict__ Wk,
                          const float* __restrict__ Wv) {
    __shared__ float row[128];
    int r = blockIdx.x, t = threadIdx.x;
    const float* proj; const float* W; float* out;
    if (r < 386)      { proj = Wq_proj + r * 128;        W = Wq; out = g_Wq_eff + r * 128; }
    else if (r < 514) { proj = Wk_proj + (r - 386) * 128; W = Wk; out = g_Wk_eff + (r - 386) * 128; }
    else              { proj = Wv_proj + (r - 514) * 128; W = Wv; out = g_Wv_eff + (r - 514) * 128; }
    row[t] = proj[t];
    __syncthreads();
    int h = t >> 4, k = t & 15;
    const float* Wb = W + h * 2048 + k;
    float a0 = 0.f, a1 = 0.f, a2 = 0.f, a3 = 0.f;
    #pragma unroll 8
    for (int m = 0; m < 128; m += 4) {
        a0 += row[m]     * __ldg(Wb + m * 16);
        a1 += row[m + 1] * __ldg(Wb + (m + 1) * 16);
        a2 += row[m + 2] * __ldg(Wb + (m + 2) * 16);
        a3 += row[m + 3] * __ldg(Wb + (m + 3) * 16);
    }
    out[t] = (a0 + a1) + (a2 + a3);
}

// ---------------- setup 2: per-(e,a) query -> w-tilde --------------------
__global__ void setup_wtil(const float* __restrict__ gc,
                           const float* __restrict__ dep,
                           const float* __restrict__ tbd,
                           const float* __restrict__ loadv) {
    __shared__ float qin[386];
    __shared__ float qh[128];
    int ea = blockIdx.x, t = threadIdx.x;
    int e = ea >> 3, a = ea & 7;
    qin[t]       = gc [e * 128 + t];
    qin[128 + t] = dep[e * 128 + t];
    qin[256 + t] = tbd[e * 128 + t];
    if (t == 0) { qin[384] = loadv[e * 8 + a]; qin[385] = (float)a; }
    __syncthreads();
    float a0 = 0.f, a1 = 0.f, a2 = 0.f, a3 = 0.f;
    #pragma unroll 4
    for (int j = 0; j < 384; j += 4) {
        a0 += qin[j]     * g_Wq_eff[j * 128 + t];
        a1 += qin[j + 1] * g_Wq_eff[(j + 1) * 128 + t];
        a2 += qin[j + 2] * g_Wq_eff[(j + 2) * 128 + t];
        a3 += qin[j + 3] * g_Wq_eff[(j + 3) * 128 + t];
    }
    a0 += qin[384] * g_Wq_eff[384 * 128 + t];
    a1 += qin[385] * g_Wq_eff[385 * 128 + t];
    qh[t] = (a0 + a1) + (a2 + a3);
    __syncthreads();
    int d = t;
    #pragma unroll
    for (int h = 0; h < 8; h++) {
        float w = 0.f;
        #pragma unroll
        for (int k = 0; k < 16; k++)
            w += qh[h * 16 + k] * g_Wk_eff[d * 128 + h * 16 + k];
        g_wtil[(ea * 8 + h) * 128 + d] = w * 0.25f;   // 1/sqrt(DK) folded in
    }
}

// ---------------- main: fused streaming attention ----------------------
// One CTA of 128 threads (4 warps) per (e,a). Each warp strides rows l.
// Lane layout: h = lane>>2 (head), g = lane&3.
// Interleaved d-mapping: lane owns floats d = i*16 + g*4 + {0..3}, i=0..7,
// so each LDG.128 (fixed i) covers 64 CONTIGUOUS bytes -> 1 L1 line.
// 4-deep register prefetch pipeline hides DRAM latency.
__global__ __launch_bounds__(128, 2)
void attn_main(const float* __restrict__ emb,
               const int*   __restrict__ lens,
               const float* __restrict__ Wo,
               float*       __restrict__ out) {
    __shared__ float sm_u[4][8][128];   // [warp][head][d]  16KB
    __shared__ float sm_m[4][8];
    __shared__ float sm_d[4][8];
    __shared__ float sm_scale[4][8];
    __shared__ float sm_den[8];
    __shared__ float sm_uf[8 * 128];
    __shared__ float sm_ctx[128];

    int ea = blockIdx.x;
    int a  = ea & 7;
    int len = lens[ea];
    len = max(1, min(len, L_));

    int tid  = threadIdx.x;
    int warp = tid >> 5, lane = tid & 31;
    int h = lane >> 2, g = lane & 3;

    // w-tilde in interleaved layout: w2[2i],w2[2i+1] = wtil[i*16+g*4 + 0..3]
    ull w2[16], u2[16];
    {
        const float* wb = g_wtil + (ea * 8 + h) * 128;
        #pragma unroll
        for (int i = 0; i < 8; i++) {
            ulonglong2 v = *(const ulonglong2*)(wb + i * 16 + g * 4);
            w2[2*i] = v.x; w2[2*i+1] = v.y;
        }
    }
    #pragma unroll
    for (int i = 0; i < 16; i++) u2[i] = 0ull;

    float m = __int_as_float(0xff800000);  // -inf (reference max)
    float denom = 0.f;
    const float* base = emb + (size_t)ea * (L_ * D_);
    int lenm1 = len - 1;

    ull xb0[16], xb1[16], xb2[16], xb3[16];

    #define LOADX(XB, ROW) do {                                              \
        int rc_ = min((ROW), lenm1);                                         \
        const ulonglong2* rp_ = (const ulonglong2*)(base + (size_t)rc_ * D_);\
        _Pragma("unroll")                                                    \
        for (int i_ = 0; i_ < 8; i_++) {                                     \
            ulonglong2 v_ = rp_[i_ * 4 + g];                                 \
            (XB)[2*i_] = v_.x; (XB)[2*i_+1] = v_.y;                          \
        }                                                                    \
    } while (0)

    #define COMPUTE(XB, ROW) do {                                            \
        if ((ROW) < len) {                                                   \
            ull sp_ = 0ull;                                                  \
            _Pragma("unroll")                                                \
            for (int i_ = 0; i_ < 16; i_++) sp_ = fma2((XB)[i_], w2[i_], sp_);\
            float s0_, s1_; unpack2(sp_, s0_, s1_);                          \
            float s_ = s0_ + s1_;                                            \
            s_ += __shfl_xor_sync(0xffffffffu, s_, 1);                       \
            s_ += __shfl_xor_sync(0xffffffffu, s_, 2);                       \
            float p_;                                                        \
            if (s_ > m) {   /* ~once: headroom makes this rare */            \
                float mn_ = s_ + 32.0f;                                      \
                float sc_ = __expf(m - mn_);     /* first: exp(-inf)=0 */    \
                denom *= sc_;                                                \
                ull sc2_ = pack2(sc_, sc_);                                  \
                _Pragma("unroll")                                            \
                for (int i_ = 0; i_ < 16; i_++) u2[i_] = mul2(u2[i_], sc2_); \
                m = mn_;                                                     \
                p_ = 1.26641655e-14f;            /* exp(-32) */              \
            } else {                                                         \
                p_ = __expf(s_ - m);                                         \
            }                                                                \
            denom += p_;                                                     \
            ull p2_ = pack2(p_, p_);                                         \
            _Pragma("unroll")                                                \
            for (int i_ = 0; i_ < 16; i_++) u2[i_] = fma2(p2_, (XB)[i_], u2[i_]);\
        }                                                                    \
    } while (0)

    // prime the pipeline (clamped loads are always in-bounds)
    LOADX(xb0, warp);
    LOADX(xb1, warp + 4);
    LOADX(xb2, warp + 8);

    for (int l = warp; l < len; l += 16) {
        LOADX(xb3, l + 12);
        COMPUTE(xb0, l);
        LOADX(xb0, l + 16);
        COMPUTE(xb1, l + 4);
        LOADX(xb1, l + 20);
        COMPUTE(xb2, l + 8);
        LOADX(xb2, l + 24);
        COMPUTE(xb3, l + 12);
    }

    // dump per-warp partials (interleaved layout -> true d index)
    {
        float* up = &sm_u[warp][h][0];
        #pragma unroll
        for (int i = 0; i < 8; i++) {
            float f0, f1, f2, f3;
            unpack2(u2[2*i],   f0, f1);
            unpack2(u2[2*i+1], f2, f3);
            *(float4*)(up + i * 16 + g * 4) = make_float4(f0, f1, f2, f3);
        }
        if (g == 0) { sm_m[warp][h] = m; sm_d[warp][h] = denom; }
    }
    __syncthreads();

    // per-head cross-warp max / denom
    if (tid < 8) {
        int hh = tid;
        float mh = __int_as_float(0xff800000);
        #pragma unroll
        for (int w = 0; w < 4; w++) mh = fmaxf(mh, sm_m[w][hh]);
        float dt = 0.f;
        #pragma unroll
        for (int w = 0; w < 4; w++) {
            float sc = __expf(sm_m[w][hh] - mh);  // empty warp: exp(-inf)=0
            sm_scale[w][hh] = sc;
            dt += sm_d[w][hh] * sc;
        }
        sm_den[hh] = dt;
    }
    __syncthreads();

    // combine u across warps
    for (int idx = tid; idx < 1024; idx += 128) {
        int hh = idx >> 7, d = idx & 127;
        float acc = 0.f;
        #pragma unroll
        for (int w = 0; w < 4; w++) acc += sm_u[w][hh][d] * sm_scale[w][hh];
        sm_uf[idx] = acc;
    }
    __syncthreads();

    // ctx[h*16+k] = (u_f[h,:]/den[h]) . Wv_eff[:, h*16+k] + a * Wv_eff[128, .]
    {
        int hh = tid >> 4;
        float a0 = 0.f, a1 = 0.f;
        #pragma unroll 8
        for (int d = 0; d < 128; d += 2) {
            a0 += sm_uf[hh * 128 + d]     * g_Wv_eff[d * 128 + tid];
            a1 += sm_uf[hh * 128 + d + 1] * g_Wv_eff[(d + 1) * 128 + tid];
        }
        sm_ctx[tid] = (a0 + a1) / sm_den[hh] + (float)a * g_Wv_eff[128 * 128 + tid];
    }
    __syncthreads();

    // out[d] = ctx . Wo[:, d]   (Wo flat [128][128])
    {
        float a0 = 0.f, a1 = 0.f;
        #pragma unroll 8
        for (int j = 0; j < 128; j += 2) {
            a0 += sm_ctx[j]     * __ldg(Wo + j * 128 + tid);
            a1 += sm_ctx[j + 1] * __ldg(Wo + (j + 1) * 128 + tid);
        }
        out[ea * 128 + tid] = a0 + a1;
    }

    #undef LOADX
    #undef COMPUTE
}

// ---------------- launch ------------------------------------------------
extern "C" void kernel_launch(void* const* d_in, const int* in_sizes, int n_in,
                              void* d_out, int out_size) {
    const float* gc      = (const float*)d_in[0];   // graph_context           [E,D]
    const float* dep     = (const float*)d_in[1];   // depot_embedding         [E,D]
    const float* tbd     = (const float*)d_in[2];   // tbd_node_embedding      [E,D]
    const float* loadv   = (const float*)d_in[3];   // multi_current_load      [E,A]
    const float* emb     = (const float*)d_in[4];   // visited embeddings      [E,A,L,D]
    const int*   lens    = (const int*)  d_in[5];   // visited lens            [E,A]
    const float* Wq_proj = (const float*)d_in[6];   // [386,128]
    const float* Wk_proj = (const float*)d_in[7];   // [129,128]
    const float* Wv_proj = (const float*)d_in[8];   // [129,128]
    const float* Wq      = (const float*)d_in[9];   // [8,128,16]
    const float* Wk      = (const float*)d_in[10];  // [8,128,16]
    const float* Wv      = (const float*)d_in[11];  // [8,128,16]
    const float* Wo      = (const float*)d_in[12];  // [8,16,128]
    float* out = (float*)d_out;                     // [E,A,D]

    setup_eff <<<643, 128>>>(Wq_proj, Wk_proj, Wv_proj, Wq, Wk, Wv);
    setup_wtil<<<EA_, 128>>>(gc, dep, tbd, loadv);
    attn_main <<<EA_, 128>>>(emb, lens, Wo, out);
}

// round 4
// speedup vs baseline: 2.4222x; 1.4322x over previous
#include <cuda_runtime.h>
#include <cuda_bf16.h>

#define E_ 64
#define A_ 8
#define L_ 2048
#define D_ 128
#define H_ 8
#define EA_ (E_*A_)
#define CHUNK_ 512
#define NC_ 4            // chunks per (e,a)

typedef unsigned long long ull;

// ---------------- device scratch ----------------
__device__ float g_Wq_eff[386 * 128];
__device__ float g_Wk_eff[128 * 128];
__device__ float g_Wv_eff[129 * 128];
__device__ float g_wtil [EA_ * H_ * 128];
// per-(ea,chunk) partials
__device__ float g_pu[EA_ * NC_ * 1024];   // [pc][h][d]
__device__ float g_pm[EA_ * NC_ * 8];
__device__ float g_pd[EA_ * NC_ * 8];

// ---------------- packed f32x2 helpers ----------
__device__ __forceinline__ ull pack2(float a, float b) {
    ull r; asm("mov.b64 %0, {%1, %2};" : "=l"(r)
               : "r"(__float_as_uint(a)), "r"(__float_as_uint(b)));
    return r;
}
__device__ __forceinline__ void unpack2(ull v, float& a, float& b) {
    unsigned int x, y;
    asm("mov.b64 {%0, %1}, %2;" : "=r"(x), "=r"(y) : "l"(v));
    a = __uint_as_float(x); b = __uint_as_float(y);
}
__device__ __forceinline__ ull fma2(ull a, ull b, ull c) {
    ull d; asm("fma.rn.f32x2 %0, %1, %2, %3;" : "=l"(d) : "l"(a), "l"(b), "l"(c));
    return d;
}
__device__ __forceinline__ ull mul2(ull a, ull b) {
    ull d; asm("mul.rn.f32x2 %0, %1, %2;" : "=l"(d) : "l"(a), "l"(b));
    return d;
}
__device__ __forceinline__ void cp_async16(unsigned int saddr, const void* g) {
    asm volatile("cp.async.cg.shared.global [%0], [%1], 16;" :: "r"(saddr), "l"(g));
}
__device__ __forceinline__ void cp_commit() { asm volatile("cp.async.commit_group;"); }
__device__ __forceinline__ void cp_wait2()  { asm volatile("cp.async.wait_group 2;"); }

// ---------------- setup 1 ----------------
__global__ void setup_eff(const float* __restrict__ Wq_proj,
                          const float* __restrict__ Wk_proj,
                          const float* __restrict__ Wv_proj,
                          const float* __restrict__ Wq,
                          const float* __restrict__ Wk,
                          const float* __restrict__ Wv) {
    __shared__ float row[128];
    int r = blockIdx.x, t = threadIdx.x;
    const float* proj; const float* W; float* out;
    if (r < 386)      { proj = Wq_proj + r * 128;        W = Wq; out = g_Wq_eff + r * 128; }
    else if (r < 514) { proj = Wk_proj + (r - 386) * 128; W = Wk; out = g_Wk_eff + (r - 386) * 128; }
    else              { proj = Wv_proj + (r - 514) * 128; W = Wv; out = g_Wv_eff + (r - 514) * 128; }
    row[t] = proj[t];
    __syncthreads();
    int h = t >> 4, k = t & 15;
    const float* Wb = W + h * 2048 + k;
    float a0 = 0.f, a1 = 0.f, a2 = 0.f, a3 = 0.f;
    #pragma unroll 8
    for (int m = 0; m < 128; m += 4) {
        a0 += row[m]     * __ldg(Wb + m * 16);
        a1 += row[m + 1] * __ldg(Wb + (m + 1) * 16);
        a2 += row[m + 2] * __ldg(Wb + (m + 2) * 16);
        a3 += row[m + 3] * __ldg(Wb + (m + 3) * 16);
    }
    out[t] = (a0 + a1) + (a2 + a3);
}

// ---------------- setup 2 ----------------
__global__ void setup_wtil(const float* __restrict__ gc,
                           const float* __restrict__ dep,
                           const float* __restrict__ tbd,
                           const float* __restrict__ loadv) {
    __shared__ float qin[386];
    __shared__ float qh[128];
    int ea = blockIdx.x, t = threadIdx.x;
    int e = ea >> 3, a = ea & 7;
    qin[t]       = gc [e * 128 + t];
    qin[128 + t] = dep[e * 128 + t];
    qin[256 + t] = tbd[e * 128 + t];
    if (t == 0) { qin[384] = loadv[e * 8 + a]; qin[385] = (float)a; }
    __syncthreads();
    float a0 = 0.f, a1 = 0.f, a2 = 0.f, a3 = 0.f;
    #pragma unroll 4
    for (int j = 0; j < 384; j += 4) {
        a0 += qin[j]     * g_Wq_eff[j * 128 + t];
        a1 += qin[j + 1] * g_Wq_eff[(j + 1) * 128 + t];
        a2 += qin[j + 2] * g_Wq_eff[(j + 2) * 128 + t];
        a3 += qin[j + 3] * g_Wq_eff[(j + 3) * 128 + t];
    }
    a0 += qin[384] * g_Wq_eff[384 * 128 + t];
    a1 += qin[385] * g_Wq_eff[385 * 128 + t];
    qh[t] = (a0 + a1) + (a2 + a3);
    __syncthreads();
    int d = t;
    #pragma unroll
    for (int h = 0; h < 8; h++) {
        float w = 0.f;
        #pragma unroll
        for (int k = 0; k < 16; k++)
            w += qh[h * 16 + k] * g_Wk_eff[d * 128 + h * 16 + k];
        g_wtil[(ea * 8 + h) * 128 + d] = w * 0.25f;
    }
}

// ---------------- attention partial: one CTA per (ea, chunk) -------------
// 128 threads (4 warps). cp.async 3-stage smem pipeline, 16 rows/stage.
// Within a stage, warp w consumes rows [w*4, w*4+4).
// Lane layout: h = lane>>2, g = lane&3; lane owns interleaved floats
// d = i*16 + g*4 + {0..3}  (matches g_wtil usage).
__global__ __launch_bounds__(128, 3)
void attn_part(const float* __restrict__ emb,
               const int*   __restrict__ lens) {
    __shared__ float stg[3][16 * 128];   // 24 KB
    __shared__ float sm_u[4][8][128];    // 16 KB
    __shared__ float sm_m[4][8];
    __shared__ float sm_d[4][8];
    __shared__ float sm_scale[4][8];

    int pc = blockIdx.x;
    int ea = pc >> 2, c = pc & 3;
    int len = lens[ea];
    len = max(1, min(len, L_));
    int c0 = c * CHUNK_;
    if (c0 >= len) return;                  // empty chunk: uniform exit
    int c1 = min(c0 + CHUNK_, len);
    int rows = c1 - c0;
    int nst = (rows + 15) >> 4;

    int tid  = threadIdx.x;
    int warp = tid >> 5, lane = tid & 31;
    int h = lane >> 2, g = lane & 3;

    const char* base = (const char*)emb + (size_t)ea * (L_ * 512);
    unsigned int stg_base = (unsigned int)__cvta_generic_to_shared(&stg[0][0]);

    #define ISSUE(S) do {                                                    \
        int s_ = (S);                                                        \
        if (s_ < nst) {                                                      \
            int r0_ = c0 + s_ * 16;                                          \
            unsigned int sb_ = stg_base + (unsigned int)((s_ % 3) * 8192);   \
            _Pragma("unroll")                                                \
            for (int k_ = 0; k_ < 4; k_++) {                                 \
                int off_ = k_ * 2048 + tid * 16;                             \
                int r_ = min(r0_ + (off_ >> 9), c1 - 1);                     \
                cp_async16(sb_ + off_, base + (size_t)r_ * 512 + (off_ & 511)); \
            }                                                                \
        }                                                                    \
        cp_commit();                                                         \
    } while (0)

    // load w-tilde (interleaved layout)
    ull w2[16], u2[16];
    {
        const float* wb = g_wtil + (ea * 8 + h) * 128;
        #pragma unroll
        for (int i = 0; i < 8; i++) {
            ulonglong2 v = *(const ulonglong2*)(wb + i * 16 + g * 4);
            w2[2*i] = v.x; w2[2*i+1] = v.y;
        }
    }
    #pragma unroll
    for (int i = 0; i < 16; i++) u2[i] = 0ull;

    float m = __int_as_float(0xff800000);
    float denom = 0.f;

    ISSUE(0); ISSUE(1); ISSUE(2);

    for (int s = 0; s < nst; s++) {
        cp_wait2();
        __syncthreads();
        const float* sbuf = stg[s % 3];
        #pragma unroll
        for (int j = 0; j < 4; j++) {
            int rl = s * 16 + warp * 4 + j;
            if (rl < rows) {
                const float* sp = sbuf + (warp * 4 + j) * 128;
                ull x2[16];
                #pragma unroll
                for (int i = 0; i < 8; i++) {
                    ulonglong2 v = *(const ulonglong2*)(sp + i * 16 + g * 4);
                    x2[2*i] = v.x; x2[2*i+1] = v.y;
                }
                ull sp2 = 0ull;
                #pragma unroll
                for (int i = 0; i < 16; i++) sp2 = fma2(x2[i], w2[i], sp2);
                float s0, s1; unpack2(sp2, s0, s1);
                float sv = s0 + s1;
                sv += __shfl_xor_sync(0xffffffffu, sv, 1);
                sv += __shfl_xor_sync(0xffffffffu, sv, 2);
                float p;
                if (sv > m) {                      // rare (32-headroom)
                    float mn = sv + 32.0f;
                    float sc = __expf(m - mn);     // first: exp(-inf)=0
                    denom *= sc;
                    ull sc2 = pack2(sc, sc);
                    #pragma unroll
                    for (int i = 0; i < 16; i++) u2[i] = mul2(u2[i], sc2);
                    m = mn;
                    p = 1.26641655e-14f;           // exp(-32)
                } else {
                    p = __expf(sv - m);
                }
                denom += p;
                ull p2 = pack2(p, p);
                #pragma unroll
                for (int i = 0; i < 16; i++) u2[i] = fma2(p2, x2[i], u2[i]);
            }
        }
        __syncthreads();
        ISSUE(s + 3);
    }

    // per-warp partials to smem (interleaved -> true d)
    {
        float* up = &sm_u[warp][h][0];
        #pragma unroll
        for (int i = 0; i < 8; i++) {
            float f0, f1, f2, f3;
            unpack2(u2[2*i],   f0, f1);
            unpack2(u2[2*i+1], f2, f3);
            *(float4*)(up + i * 16 + g * 4) = make_float4(f0, f1, f2, f3);
        }
        if (g == 0) { sm_m[warp][h] = m; sm_d[warp][h] = denom; }
    }
    __syncthreads();

    // cross-warp merge -> chunk partial
    if (tid < 8) {
        int hh = tid;
        float mh = __int_as_float(0xff800000);
        #pragma unroll
        for (int w = 0; w < 4; w++) mh = fmaxf(mh, sm_m[w][hh]);
        float dt = 0.f;
        #pragma unroll
        for (int w = 0; w < 4; w++) {
            float sc = __expf(sm_m[w][hh] - mh);
            sm_scale[w][hh] = sc;
            dt += sm_d[w][hh] * sc;
        }
        g_pm[pc * 8 + hh] = mh;
        g_pd[pc * 8 + hh] = dt;
    }
    __syncthreads();

    for (int idx = tid; idx < 1024; idx += 128) {
        int hh = idx >> 7, d = idx & 127;
        float acc = 0.f;
        #pragma unroll
        for (int w = 0; w < 4; w++) acc += sm_u[w][hh][d] * sm_scale[w][hh];
        g_pu[pc * 1024 + idx] = acc;
    }
    #undef ISSUE
}

// ---------------- combine + epilogue: one CTA per (e,a) -----------------
__global__ __launch_bounds__(128)
void combine(const int* __restrict__ lens,
             const float* __restrict__ Wo,
             float* __restrict__ out) {
    __shared__ float scale[NC_][8];
    __shared__ float den[8];
    __shared__ float uf[1024];
    __shared__ float ctx[128];

    int ea = blockIdx.x, tid = threadIdx.x;
    int a = ea & 7;
    int len = lens[ea];
    len = max(1, min(len, L_));
    int nc = (len + CHUNK_ - 1) >> 9;

    if (tid < 8) {
        int hh = tid;
        float M = __int_as_float(0xff800000);
        for (int c = 0; c < nc; c++) M = fmaxf(M, g_pm[(ea * NC_ + c) * 8 + hh]);
        float dt = 0.f;
        for (int c = 0; c < nc; c++) {
            float sc = __expf(g_pm[(ea * NC_ + c) * 8 + hh] - M);
            scale[c][hh] = sc;
            dt += g_pd[(ea * NC_ + c) * 8 + hh] * sc;
        }
        den[hh] = dt;
    }
    __syncthreads();

    for (int idx = tid; idx < 1024; idx += 128) {
        int hh = idx >> 7;
        float acc = 0.f;
        for (int c = 0; c < nc; c++)
            acc += g_pu[(ea * NC_ + c) * 1024 + idx] * scale[c][hh];
        uf[idx] = acc;
    }
    __syncthreads();

    // ctx[h*16+k] = (uf[h,:]/den[h]) . Wv_eff[:, h*16+k] + a * Wv_eff[128, .]
    {
        int hh = tid >> 4;
        float a0 = 0.f, a1 = 0.f;
        #pragma unroll 8
        for (int d = 0; d < 128; d += 2) {
            a0 += uf[hh * 128 + d]     * g_Wv_eff[d * 128 + tid];
            a1 += uf[hh * 128 + d + 1] * g_Wv_eff[(d + 1) * 128 + tid];
        }
        ctx[tid] = (a0 + a1) / den[hh] + (float)a * g_Wv_eff[128 * 128 + tid];
    }
    __syncthreads();

    {
        float a0 = 0.f, a1 = 0.f;
        #pragma unroll 8
        for (int j = 0; j < 128; j += 2) {
            a0 += ctx[j]     * __ldg(Wo + j * 128 + tid);
            a1 += ctx[j + 1] * __ldg(Wo + (j + 1) * 128 + tid);
        }
        out[ea * 128 + tid] = a0 + a1;
    }
}

// ---------------- launch ------------------------------------------------
extern "C" void kernel_launch(void* const* d_in, const int* in_sizes, int n_in,
                              void* d_out, int out_size) {
    const float* gc      = (const float*)d_in[0];
    const float* dep     = (const float*)d_in[1];
    const float* tbd     = (const float*)d_in[2];
    const float* loadv   = (const float*)d_in[3];
    const float* emb     = (const float*)d_in[4];
    const int*   lens    = (const int*)  d_in[5];
    const float* Wq_proj = (const float*)d_in[6];
    const float* Wk_proj = (const float*)d_in[7];
    const float* Wv_proj = (const float*)d_in[8];
    const float* Wq      = (const float*)d_in[9];
    const float* Wk      = (const float*)d_in[10];
    const float* Wv      = (const float*)d_in[11];
    const float* Wo      = (const float*)d_in[12];
    float* out = (float*)d_out;

    setup_eff <<<643, 128>>>(Wq_proj, Wk_proj, Wv_proj, Wq, Wk, Wv);
    setup_wtil<<<EA_, 128>>>(gc, dep, tbd, loadv);
    attn_part <<<EA_ * NC_, 128>>>(emb, lens);
    combine   <<<EA_, 128>>>(lens, Wo, out);
}